// round 14
// baseline (speedup 1.0000x reference)
#include <cuda_runtime.h>
#include <cuda_fp16.h>
#include <cstdint>

// ---------------------------------------------------------------------------
// Problem constants
// ---------------------------------------------------------------------------
#define B     8
#define CIN   64
#define CH    64
#define HH    128
#define WW    128
#define CS    128              // CIN + CH
#define COUT  256              // 4 * CH
#define HW    (HH * WW)
#define KTOT  1152             // CS * 9
#define NCHUNK 18              // 2 halves x 9 taps (K=64 each)
#define NTOT  (B * CH * HW)

// CTA tile: M=64 px, N=128 gate-rows (all 4 gates x 32 channels)
#define MT    64
#define NT    128

// SMEM layout (pitch 144B = 9 x 16B banks -> conflict-free ldmatrix)
#define PITCH  144
#define AROW   (66 * PITCH)           //  9504 B: one input row, 66 px x 64ch
#define A_HALF (3 * AROW)             // 28512 B
#define A_TOT  (2 * A_HALF)           // 57024 B
#define B_TILE (NT * PITCH)           // 18432 B
#define NBSTG  3
#define OFF_B  A_TOT
#define SMEM_TOTAL (A_TOT + NBSTG * B_TILE)   // 112320 B -> 2 CTAs/SM
#define GPITCH 129                    // fp32 gate staging pitch (aliases base)

// ---------------------------------------------------------------------------
// Device scratch
// ---------------------------------------------------------------------------
__device__ __half g_inT[(size_t)B * HH * WW * CS];   // [b][y][x][ci] fp16
__device__ __half g_w[(size_t)COUT * KTOT];          // [n][k], n gate-interleaved

// ---------------------------------------------------------------------------
// Helpers (base ISA only)
// ---------------------------------------------------------------------------
__device__ __forceinline__ uint32_t smem_to_u32(const void* p) {
    uint32_t a;
    asm("{ .reg .u64 t; cvta.to.shared.u64 t, %1; cvt.u32.u64 %0, t; }"
        : "=r"(a) : "l"(p));
    return a;
}

__device__ __forceinline__ void cp16(uint32_t dst, const void* src, bool valid) {
    int sz = valid ? 16 : 0;
    asm volatile("cp.async.cg.shared.global [%0], [%1], 16, %2;"
                 :: "r"(dst), "l"(src), "r"(sz) : "memory");
}

#define CP_COMMIT() asm volatile("cp.async.commit_group;" ::: "memory")
#define CP_WAIT1()  asm volatile("cp.async.wait_group 1;" ::: "memory")

#define LDSM_X4(r, addr) \
    asm volatile("ldmatrix.sync.aligned.m8n8.x4.shared.b16 {%0,%1,%2,%3}, [%4];" \
        : "=r"((r)[0]), "=r"((r)[1]), "=r"((r)[2]), "=r"((r)[3]) : "r"(addr))

__device__ __forceinline__ void mma_fp16(float* d, const uint32_t* a,
                                         uint32_t b0, uint32_t b1) {
    asm volatile(
        "mma.sync.aligned.m16n8k16.row.col.f32.f16.f16.f32 "
        "{%0,%1,%2,%3}, {%4,%5,%6,%7}, {%8,%9}, {%0,%1,%2,%3};"
        : "+f"(d[0]), "+f"(d[1]), "+f"(d[2]), "+f"(d[3])
        : "r"(a[0]), "r"(a[1]), "r"(a[2]), "r"(a[3]), "r"(b0), "r"(b1));
}

__device__ __forceinline__ float sigm_f(float v) { return 1.f / (1.f + __expf(-v)); }
__device__ __forceinline__ float tanh_f(float v) { return 2.f / (1.f + __expf(-2.f * v)) - 1.f; }

// ---------------------------------------------------------------------------
// Prep 1: transpose concat(x, prev_h) -> [b][y][x][ci] fp16 (float4 loads)
// ---------------------------------------------------------------------------
__global__ __launch_bounds__(256)
void prep_input_kernel(const float* __restrict__ x, const float* __restrict__ ph)
{
    __shared__ float s[64][129];
    const int bid = blockIdx.x;
    const int b = bid >> 7, y = bid & 127;
    const int tid = threadIdx.x;

    #pragma unroll
    for (int h2 = 0; h2 < 2; ++h2) {
        const int cbase = h2 * 64;
        for (int idx = tid; idx < 64 * 32; idx += 256) {
            int ci = idx >> 5, x4 = (idx & 31) * 4;
            int cs = cbase + ci;
            const float* src = (cs < CIN)
                ? (x  + ((size_t)b * CIN + cs) * HW)
                : (ph + ((size_t)b * CH + (cs - CIN)) * HW);
            float4 v = *reinterpret_cast<const float4*>(src + y * WW + x4);
            s[ci][x4]     = v.x;
            s[ci][x4 + 1] = v.y;
            s[ci][x4 + 2] = v.z;
            s[ci][x4 + 3] = v.w;
        }
        __syncthreads();
        for (int idx = tid; idx < 128 * 32; idx += 256) {
            int xx = idx >> 5, cp = (idx & 31) * 2;
            __half2 v = __floats2half2_rn(s[cp][xx], s[cp + 1][xx]);
            size_t o = ((size_t)(b * HH + y) * WW + xx) * CS + cbase + cp;
            *reinterpret_cast<__half2*>(g_inT + o) = v;
        }
        __syncthreads();
    }
}

// ---------------------------------------------------------------------------
// Prep 2: weights -> [n][k=tap*128+cs], fp16, gate-interleaved N order:
//   n = (c>>5)*128 + gate*32 + (c&31)   (oc = gate*64 + c)
// ---------------------------------------------------------------------------
__global__ __launch_bounds__(256)
void prep_w_kernel(const float* __restrict__ Wg)
{
    int idx = blockIdx.x * blockDim.x + threadIdx.x;
    if (idx >= COUT * KTOT) return;
    int n = idx / KTOT, k = idx - n * KTOT;
    int tap = k >> 7, cs = k & 127;
    int chblk = n >> 7, gate = (n >> 5) & 3, cl = n & 31;
    int oc = gate * 64 + chblk * 32 + cl;
    g_w[idx] = __float2half_rn(Wg[(size_t)oc * KTOT + cs * 9 + tap]);
}

// ---------------------------------------------------------------------------
// Main: implicit-GEMM conv (fp16) + fused LSTM gating.
// CTA tile M=64 x N=128, K=1152; 2 CTAs/SM.
// 128 threads = 4 warps in 2(M) x 2(N); warp tile 32x64.
// Single __syncthreads per chunk (issue-after-barrier, NBSTG=3 safe).
// ---------------------------------------------------------------------------
__device__ __forceinline__ void issue_A_half(int half, uint32_t sb,
                                             int b, int y, int mx0, int tid)
{
    const int ci0 = half * 64;
    const uint32_t abase = sb + half * A_HALF;
    // 3 rows x 66 px x 8 segs = 1584 cp.async -> 13/thread (guarded)
    #pragma unroll
    for (int q = 0; q < 13; ++q) {
        int idx = q * 128 + tid;
        if (idx < 1584) {
            int r = idx / 528;                   // row 0..2
            int rem = idx - r * 528;
            int pxi = rem >> 3, seg = rem & 7;   // pxi 0..65
            int yy = y + r - 1;
            int px = mx0 + pxi - 1;
            bool valid = ((unsigned)yy < (unsigned)HH) &
                         ((unsigned)px < (unsigned)WW);
            int yc = ((unsigned)yy < (unsigned)HH) ? yy : 0;
            int xc = ((unsigned)px < (unsigned)WW) ? px : 0;
            const void* src = g_inT + (((size_t)(b * HH + yc) * WW + xc) * CS
                                       + ci0 + seg * 8);
            uint32_t dst = abase + r * AROW + pxi * PITCH + seg * 16;
            cp16(dst, src, valid);
        }
    }
}

__device__ __forceinline__ void issue_B(int chunk, uint32_t sb, int n0, int tid)
{
    const int half = chunk / 9, tap = chunk - half * 9;
    const uint32_t bbase = sb + OFF_B + (chunk % NBSTG) * B_TILE;
    // 128 rows x 8 segs = 1024 -> 8/thread
    #pragma unroll
    for (int q = 0; q < 8; ++q) {
        int idx = q * 128 + tid;
        int n = idx >> 3, seg = idx & 7;
        const void* src = g_w + ((size_t)(n0 + n) * KTOT + tap * 128 + half * 64
                                 + seg * 8);
        uint32_t dst = bbase + n * PITCH + seg * 16;
        cp16(dst, src, true);
    }
}

__global__ __launch_bounds__(128, 2)
void convlstm_mma_kernel(const float* __restrict__ prev_c,
                         const float* __restrict__ bg,
                         float* __restrict__ out)
{
    extern __shared__ char smem[];
    const uint32_t sb = smem_to_u32(smem);
    const int tid = threadIdx.x, wid = tid >> 5, lane = tid & 31;
    const int bid = blockIdx.x;
    const int mhalf = bid & 1, nhalf = (bid >> 1) & 1;
    const int y = (bid >> 2) & 127, b = bid >> 9;
    const int mx0 = mhalf * MT;           // pixel-tile origin
    const int nb0 = nhalf * NT;           // weight-row origin
    const int m0 = (wid & 1) * 32;        // warp m origin (2 m-warps)
    const int n0w = (wid >> 1) * 64;      // warp n origin (2 n-warps)

    float acc[2][8][4];
    #pragma unroll
    for (int i = 0; i < 2; ++i)
        #pragma unroll
        for (int j = 0; j < 8; ++j)
            #pragma unroll
            for (int t = 0; t < 4; ++t) acc[i][j][t] = 0.f;

    // Prologue: g1 = {A0, B0}, g2 = {A1, B1}
    issue_A_half(0, sb, b, y, mx0, tid);
    issue_B(0, sb, nb0, tid);
    CP_COMMIT();
    issue_A_half(1, sb, b, y, mx0, tid);
    issue_B(1, sb, nb0, tid);
    CP_COMMIT();

    for (int c = 0; c < NCHUNK; ++c) {
        CP_WAIT1();                // group holding B(c) complete
        __syncthreads();           // visibility + stage-reuse safety
        if (c + 2 < NCHUNK) issue_B(c + 2, sb, nb0, tid);
        CP_COMMIT();

        const int half = c / 9, tap = c - half * 9;
        const int ky = tap / 3, kx = tap - ky * 3;
        const uint32_t Arow = sb + half * A_HALF + ky * AROW;
        const uint32_t Bt = sb + OFF_B + (c % NBSTG) * B_TILE;

        #pragma unroll
        for (int s = 0; s < 4; ++s) {           // 4 x k16 steps per chunk
            uint32_t af[2][4];
            #pragma unroll
            for (int i = 0; i < 2; ++i) {
                // staged px index = local px + 1; read px = m + kx - 1
                uint32_t r = m0 + i * 16 + (lane & 15) + kx;
                uint32_t off = r * PITCH + s * 32 + (lane >> 4) * 16;
                LDSM_X4(af[i], Arow + off);
            }
            uint32_t bf[4][4];
            #pragma unroll
            for (int j2 = 0; j2 < 4; ++j2) {    // 4 n16 blocks (n64 tile)
                uint32_t n = n0w + j2 * 16 + ((lane >> 4) << 3) + (lane & 7);
                uint32_t off = n * PITCH + s * 32 + ((lane >> 3) & 1) * 16;
                LDSM_X4(bf[j2], Bt + off);
            }
            #pragma unroll
            for (int i = 0; i < 2; ++i)
                #pragma unroll
                for (int j = 0; j < 8; ++j) {   // 8 n8 tiles
                    uint32_t b0 = bf[j >> 1][(j & 1) * 2];
                    uint32_t b1 = bf[j >> 1][(j & 1) * 2 + 1];
                    mma_fp16(acc[i][j], af[i], b0, b1);
                }
        }
    }
    __syncthreads();               // all warps done reading A/B smem

    // ---- epilogue: acc -> smem gate staging [px][n] fp32, pitch 129 ----
    float* sg = (float*)smem;
    #pragma unroll
    for (int i = 0; i < 2; ++i)
        #pragma unroll
        for (int j = 0; j < 8; ++j) {
            int row = m0 + i * 16 + (lane >> 2);
            int col = n0w + j * 8 + (lane & 3) * 2;
            sg[row * GPITCH + col]           = acc[i][j][0];
            sg[row * GPITCH + col + 1]       = acc[i][j][1];
            sg[(row + 8) * GPITCH + col]     = acc[i][j][2];
            sg[(row + 8) * GPITCH + col + 1] = acc[i][j][3];
        }
    __syncthreads();

    // ---- fused LSTM gating: 64 px x 32 channels, all 4 gates local ----
    const int px = tid & 63;
    const int grp = tid >> 6;                 // 0..1
    #pragma unroll
    for (int t = 0; t < 16; ++t) {
        int cl = grp * 16 + t;                // 0..31
        float gi = sg[px * GPITCH + cl]       + __ldg(&bg[nhalf * 32 + cl]);
        float gf = sg[px * GPITCH + 32 + cl]  + __ldg(&bg[64 + nhalf * 32 + cl]);
        float go = sg[px * GPITCH + 64 + cl]  + __ldg(&bg[128 + nhalf * 32 + cl]);
        float gg = sg[px * GPITCH + 96 + cl]  + __ldg(&bg[192 + nhalf * 32 + cl]);
        float ig = sigm_f(gi), fg = sigm_f(gf), og = sigm_f(go), cg = tanh_f(gg);
        int cgl = nhalf * 32 + cl;
        size_t idx = ((size_t)(b * CH + cgl)) * HW + y * WW + mx0 + px;
        float pc = prev_c[idx];
        float cell = ig * cg + fg * pc;
        float hid  = og * tanh_f(cell);
        out[idx] = hid;
        out[(size_t)NTOT + idx] = cell;
    }
}

// ---------------------------------------------------------------------------
extern "C" void kernel_launch(void* const* d_in, const int* in_sizes, int n_in,
                              void* d_out, int out_size)
{
    const float* x      = (const float*)d_in[0];
    const float* prev_h = (const float*)d_in[1];
    const float* prev_c = (const float*)d_in[2];
    const float* Wg     = (const float*)d_in[3];
    const float* bg     = (const float*)d_in[4];
    float* out = (float*)d_out;

    static bool attr_done = false;
    if (!attr_done) {
        cudaFuncSetAttribute(convlstm_mma_kernel,
                             cudaFuncAttributeMaxDynamicSharedMemorySize, SMEM_TOTAL);
        attr_done = true;
    }

    prep_input_kernel<<<B * HH, 256>>>(x, prev_h);
    prep_w_kernel<<<(COUT * KTOT + 255) / 256, 256>>>(Wg);
    convlstm_mma_kernel<<<B * HH * 4, 128, SMEM_TOTAL>>>(prev_c, bg, out);
}

// round 15
// speedup vs baseline: 1.2212x; 1.2212x over previous
#include <cuda_runtime.h>
#include <cuda_fp16.h>
#include <cstdint>

// ---------------------------------------------------------------------------
// Problem constants
// ---------------------------------------------------------------------------
#define B     8
#define CIN   64
#define CH    64
#define HH    128
#define WW    128
#define CS    128              // CIN + CH
#define COUT  256              // 4 * CH
#define HW    (HH * WW)
#define KTOT  1152             // CS * 9
#define NCHUNK 18              // 2 halves x 9 taps (K=64 each)
#define NTOT  (B * CH * HW)

// CTA tile: M=64 px, N=128 gate-rows (all 4 gates x 32 channels)
#define MT    64
#define NT    128

// SMEM layout (pitch 144B = 9 x 16B banks -> conflict-free ldmatrix)
#define PITCH  144
#define AROW   (66 * PITCH)           //  9504 B: one input row, 66 px x 64ch
#define A_HALF (3 * AROW)             // 28512 B
#define A_TOT  (2 * A_HALF)           // 57024 B
#define B_TILE (NT * PITCH)           // 18432 B
#define NBSTG  3
#define OFF_B  A_TOT
#define SMEM_TOTAL (A_TOT + NBSTG * B_TILE)   // 112320 B -> 2 CTAs/SM
#define GPITCH 129                    // fp32 gate staging pitch (aliases base)

// ---------------------------------------------------------------------------
// Device scratch
// ---------------------------------------------------------------------------
__device__ __half g_inT[(size_t)B * HH * WW * CS];   // [b][y][x][ci] fp16
__device__ __half g_w[(size_t)COUT * KTOT];          // [n][k], n gate-interleaved

// ---------------------------------------------------------------------------
// Helpers (base ISA only)
// ---------------------------------------------------------------------------
__device__ __forceinline__ uint32_t smem_to_u32(const void* p) {
    uint32_t a;
    asm("{ .reg .u64 t; cvta.to.shared.u64 t, %1; cvt.u32.u64 %0, t; }"
        : "=r"(a) : "l"(p));
    return a;
}

__device__ __forceinline__ void cp16(uint32_t dst, const void* src, bool valid) {
    int sz = valid ? 16 : 0;
    asm volatile("cp.async.cg.shared.global [%0], [%1], 16, %2;"
                 :: "r"(dst), "l"(src), "r"(sz) : "memory");
}

#define CP_COMMIT() asm volatile("cp.async.commit_group;" ::: "memory")
#define CP_WAIT1()  asm volatile("cp.async.wait_group 1;" ::: "memory")

#define LDSM_X4(r, addr) \
    asm volatile("ldmatrix.sync.aligned.m8n8.x4.shared.b16 {%0,%1,%2,%3}, [%4];" \
        : "=r"((r)[0]), "=r"((r)[1]), "=r"((r)[2]), "=r"((r)[3]) : "r"(addr))

__device__ __forceinline__ void mma_fp16(float* d, const uint32_t* a,
                                         uint32_t b0, uint32_t b1) {
    asm volatile(
        "mma.sync.aligned.m16n8k16.row.col.f32.f16.f16.f32 "
        "{%0,%1,%2,%3}, {%4,%5,%6,%7}, {%8,%9}, {%0,%1,%2,%3};"
        : "+f"(d[0]), "+f"(d[1]), "+f"(d[2]), "+f"(d[3])
        : "r"(a[0]), "r"(a[1]), "r"(a[2]), "r"(a[3]), "r"(b0), "r"(b1));
}

__device__ __forceinline__ float sigm_f(float v) { return 1.f / (1.f + __expf(-v)); }
__device__ __forceinline__ float tanh_f(float v) { return 2.f / (1.f + __expf(-2.f * v)) - 1.f; }

// ---------------------------------------------------------------------------
// Prep 1: transpose concat(x, prev_h) -> [b][y][x][ci] fp16 (float4 loads)
// ---------------------------------------------------------------------------
__global__ __launch_bounds__(256)
void prep_input_kernel(const float* __restrict__ x, const float* __restrict__ ph)
{
    __shared__ float s[64][129];
    const int bid = blockIdx.x;
    const int b = bid >> 7, y = bid & 127;
    const int tid = threadIdx.x;

    #pragma unroll
    for (int h2 = 0; h2 < 2; ++h2) {
        const int cbase = h2 * 64;
        for (int idx = tid; idx < 64 * 32; idx += 256) {
            int ci = idx >> 5, x4 = (idx & 31) * 4;
            int cs = cbase + ci;
            const float* src = (cs < CIN)
                ? (x  + ((size_t)b * CIN + cs) * HW)
                : (ph + ((size_t)b * CH + (cs - CIN)) * HW);
            float4 v = *reinterpret_cast<const float4*>(src + y * WW + x4);
            s[ci][x4]     = v.x;
            s[ci][x4 + 1] = v.y;
            s[ci][x4 + 2] = v.z;
            s[ci][x4 + 3] = v.w;
        }
        __syncthreads();
        for (int idx = tid; idx < 128 * 32; idx += 256) {
            int xx = idx >> 5, cp = (idx & 31) * 2;
            __half2 v = __floats2half2_rn(s[cp][xx], s[cp + 1][xx]);
            size_t o = ((size_t)(b * HH + y) * WW + xx) * CS + cbase + cp;
            *reinterpret_cast<__half2*>(g_inT + o) = v;
        }
        __syncthreads();
    }
}

// ---------------------------------------------------------------------------
// Prep 2: weights -> [n][k=tap*128+cs], fp16, gate-interleaved N order:
//   n = (c>>5)*128 + gate*32 + (c&31)   (oc = gate*64 + c)
// ---------------------------------------------------------------------------
__global__ __launch_bounds__(256)
void prep_w_kernel(const float* __restrict__ Wg)
{
    int idx = blockIdx.x * blockDim.x + threadIdx.x;
    if (idx >= COUT * KTOT) return;
    int n = idx / KTOT, k = idx - n * KTOT;
    int tap = k >> 7, cs = k & 127;
    int chblk = n >> 7, gate = (n >> 5) & 3, cl = n & 31;
    int oc = gate * 64 + chblk * 32 + cl;
    g_w[idx] = __float2half_rn(Wg[(size_t)oc * KTOT + cs * 9 + tap]);
}

// ---------------------------------------------------------------------------
// Main: implicit-GEMM conv (fp16) + fused LSTM gating.
// CTA tile M=64 x N=128, K=1152; 2 CTAs/SM (16 warps/SM).
// 256 threads = 8 warps in 2(M) x 4(N); warp tile 32x32.
// ONE __syncthreads per chunk: wait -> barrier -> issue(c+2) -> commit -> mma.
// Stage safety: writes at c hit stage (c+2)%3 == (c-1)%3, fully read before
// this chunk's barrier (all warps passed compute(c-1) in program order).
// ---------------------------------------------------------------------------
__device__ __forceinline__ void issue_A_half(int half, uint32_t sb,
                                             int b, int y, int mx0, int tid)
{
    const int ci0 = half * 64;
    const uint32_t abase = sb + half * A_HALF;
    // 3 rows x 66 px x 8 segs = 1584 cp.async
    #pragma unroll
    for (int q = 0; q < 7; ++q) {
        int idx = q * 256 + tid;
        if (idx < 1584) {
            int r = idx / 528;                   // row 0..2
            int rem = idx - r * 528;
            int pxi = rem >> 3, seg = rem & 7;   // pxi 0..65
            int yy = y + r - 1;
            int px = mx0 + pxi - 1;
            bool valid = ((unsigned)yy < (unsigned)HH) &
                         ((unsigned)px < (unsigned)WW);
            int yc = ((unsigned)yy < (unsigned)HH) ? yy : 0;
            int xc = ((unsigned)px < (unsigned)WW) ? px : 0;
            const void* src = g_inT + (((size_t)(b * HH + yc) * WW + xc) * CS
                                       + ci0 + seg * 8);
            uint32_t dst = abase + r * AROW + pxi * PITCH + seg * 16;
            cp16(dst, src, valid);
        }
    }
}

__device__ __forceinline__ void issue_B(int chunk, uint32_t sb, int n0, int tid)
{
    const int half = chunk / 9, tap = chunk - half * 9;
    const uint32_t bbase = sb + OFF_B + (chunk % NBSTG) * B_TILE;
    // 128 rows x 8 segs = 1024 -> 4/thread
    #pragma unroll
    for (int q = 0; q < 4; ++q) {
        int idx = q * 256 + tid;
        int n = idx >> 3, seg = idx & 7;
        const void* src = g_w + ((size_t)(n0 + n) * KTOT + tap * 128 + half * 64
                                 + seg * 8);
        uint32_t dst = bbase + n * PITCH + seg * 16;
        cp16(dst, src, true);
    }
}

__global__ __launch_bounds__(256, 2)
void convlstm_mma_kernel(const float* __restrict__ prev_c,
                         const float* __restrict__ bg,
                         float* __restrict__ out)
{
    extern __shared__ char smem[];
    const uint32_t sb = smem_to_u32(smem);
    const int tid = threadIdx.x, wid = tid >> 5, lane = tid & 31;
    const int bid = blockIdx.x;
    const int mhalf = bid & 1, nhalf = (bid >> 1) & 1;
    const int y = (bid >> 2) & 127, b = bid >> 9;
    const int mx0 = mhalf * MT;           // pixel-tile origin
    const int nb0 = nhalf * NT;           // weight-row origin
    const int m0 = (wid & 1) * 32;        // warp m origin (2 m-warps)
    const int n0w = (wid >> 1) * 32;      // warp n origin (4 n-warps)

    float acc[2][4][4];
    #pragma unroll
    for (int i = 0; i < 2; ++i)
        #pragma unroll
        for (int j = 0; j < 4; ++j)
            #pragma unroll
            for (int t = 0; t < 4; ++t) acc[i][j][t] = 0.f;

    // Prologue: g1 = {A0, B0}, g2 = {A1, B1}
    issue_A_half(0, sb, b, y, mx0, tid);
    issue_B(0, sb, nb0, tid);
    CP_COMMIT();
    issue_A_half(1, sb, b, y, mx0, tid);
    issue_B(1, sb, nb0, tid);
    CP_COMMIT();

    for (int c = 0; c < NCHUNK; ++c) {
        CP_WAIT1();                // group holding B(c) (+A) complete
        __syncthreads();           // visibility + stage-reuse safety
        if (c + 2 < NCHUNK) issue_B(c + 2, sb, nb0, tid);
        CP_COMMIT();

        const int half = c / 9, tap = c - half * 9;
        const int ky = tap / 3, kx = tap - ky * 3;
        const uint32_t Arow = sb + half * A_HALF + ky * AROW;
        const uint32_t Bt = sb + OFF_B + (c % NBSTG) * B_TILE;

        #pragma unroll
        for (int s = 0; s < 4; ++s) {           // 4 x k16 steps per chunk
            uint32_t af[2][4];
            #pragma unroll
            for (int i = 0; i < 2; ++i) {
                // staged px index = local px + 1; read px = m + kx - 1
                uint32_t r = m0 + i * 16 + (lane & 15) + kx;
                uint32_t off = r * PITCH + s * 32 + (lane >> 4) * 16;
                LDSM_X4(af[i], Arow + off);
            }
            uint32_t bf[2][4];
            #pragma unroll
            for (int j2 = 0; j2 < 2; ++j2) {    // 2 n16 blocks
                uint32_t n = n0w + j2 * 16 + ((lane >> 4) << 3) + (lane & 7);
                uint32_t off = n * PITCH + s * 32 + ((lane >> 3) & 1) * 16;
                LDSM_X4(bf[j2], Bt + off);
            }
            #pragma unroll
            for (int i = 0; i < 2; ++i)
                #pragma unroll
                for (int j = 0; j < 4; ++j) {   // 4 n8 tiles
                    uint32_t b0 = bf[j >> 1][(j & 1) * 2];
                    uint32_t b1 = bf[j >> 1][(j & 1) * 2 + 1];
                    mma_fp16(acc[i][j], af[i], b0, b1);
                }
        }
    }
    __syncthreads();               // all warps done reading A/B smem

    // ---- epilogue: acc -> smem gate staging [px][n] fp32, pitch 129 ----
    float* sg = (float*)smem;
    #pragma unroll
    for (int i = 0; i < 2; ++i)
        #pragma unroll
        for (int j = 0; j < 4; ++j) {
            int row = m0 + i * 16 + (lane >> 2);
            int col = n0w + j * 8 + (lane & 3) * 2;
            sg[row * GPITCH + col]           = acc[i][j][0];
            sg[row * GPITCH + col + 1]       = acc[i][j][1];
            sg[(row + 8) * GPITCH + col]     = acc[i][j][2];
            sg[(row + 8) * GPITCH + col + 1] = acc[i][j][3];
        }
    __syncthreads();

    // ---- fused LSTM gating: 64 px x 32 channels, all 4 gates local ----
    const int px = tid & 63;
    const int grp = tid >> 6;                 // 0..3
    #pragma unroll
    for (int t = 0; t < 8; ++t) {
        int cl = grp * 8 + t;                 // 0..31
        float gi = sg[px * GPITCH + cl]       + __ldg(&bg[nhalf * 32 + cl]);
        float gf = sg[px * GPITCH + 32 + cl]  + __ldg(&bg[64 + nhalf * 32 + cl]);
        float go = sg[px * GPITCH + 64 + cl]  + __ldg(&bg[128 + nhalf * 32 + cl]);
        float gg = sg[px * GPITCH + 96 + cl]  + __ldg(&bg[192 + nhalf * 32 + cl]);
        float ig = sigm_f(gi), fg = sigm_f(gf), og = sigm_f(go), cg = tanh_f(gg);
        int cgl = nhalf * 32 + cl;
        size_t idx = ((size_t)(b * CH + cgl)) * HW + y * WW + mx0 + px;
        float pc = prev_c[idx];
        float cell = ig * cg + fg * pc;
        float hid  = og * tanh_f(cell);
        out[idx] = hid;
        out[(size_t)NTOT + idx] = cell;
    }
}

// ---------------------------------------------------------------------------
extern "C" void kernel_launch(void* const* d_in, const int* in_sizes, int n_in,
                              void* d_out, int out_size)
{
    const float* x      = (const float*)d_in[0];
    const float* prev_h = (const float*)d_in[1];
    const float* prev_c = (const float*)d_in[2];
    const float* Wg     = (const float*)d_in[3];
    const float* bg     = (const float*)d_in[4];
    float* out = (float*)d_out;

    static bool attr_done = false;
    if (!attr_done) {
        cudaFuncSetAttribute(convlstm_mma_kernel,
                             cudaFuncAttributeMaxDynamicSharedMemorySize, SMEM_TOTAL);
        attr_done = true;
    }

    prep_input_kernel<<<B * HH, 256>>>(x, prev_h);
    prep_w_kernel<<<(COUT * KTOT + 255) / 256, 256>>>(Wg);
    convlstm_mma_kernel<<<B * HH * 4, 256, SMEM_TOTAL>>>(prev_c, bg, out);
}

// round 17
// speedup vs baseline: 1.4461x; 1.1842x over previous
#include <cuda_runtime.h>
#include <cuda_fp16.h>
#include <cstdint>

// ---------------------------------------------------------------------------
// Problem constants
// ---------------------------------------------------------------------------
#define B     8
#define CIN   64
#define CH    64
#define HH    128
#define WW    128
#define CS    128              // CIN + CH
#define COUT  256              // 4 * CH
#define HW    (HH * WW)
#define KTOT  1152             // CS * 9
#define NCHUNK 18              // 2 halves x 9 taps (K=64 each)
#define NTOT  (B * CH * HW)

// CTA tile: M=128 px (full row), N=128 gate-rows (all 4 gates x 32 channels)
#define MT    128
#define NT    128

// SMEM layout (pitch 144B = 9 x 16B banks -> conflict-free ldmatrix)
#define PITCH  144
#define AROW   (130 * PITCH)          // 18720 B: one input row, 130 px x 64ch
#define A_TOT  (3 * AROW)             // 56160 B: rows y-1,y,y+1 (ONE ci-half)
#define B_TILE (NT * PITCH)           // 18432 B
#define NBSTG  3
#define OFF_B  A_TOT
#define SMEM_TOTAL (A_TOT + NBSTG * B_TILE)   // 111456 B -> 2 CTAs/SM
#define GPITCH 129                    // fp32 gate staging pitch (aliases base)

// ---------------------------------------------------------------------------
// Device scratch
// ---------------------------------------------------------------------------
__device__ __half g_inT[(size_t)B * HH * WW * CS];   // [b][y][x][ci] fp16
__device__ __half g_w[(size_t)COUT * KTOT];          // [n][k], n gate-interleaved

// ---------------------------------------------------------------------------
// Helpers (base ISA only)
// ---------------------------------------------------------------------------
__device__ __forceinline__ uint32_t smem_to_u32(const void* p) {
    uint32_t a;
    asm("{ .reg .u64 t; cvta.to.shared.u64 t, %1; cvt.u32.u64 %0, t; }"
        : "=r"(a) : "l"(p));
    return a;
}

__device__ __forceinline__ void cp16(uint32_t dst, const void* src, bool valid) {
    int sz = valid ? 16 : 0;
    asm volatile("cp.async.cg.shared.global [%0], [%1], 16, %2;"
                 :: "r"(dst), "l"(src), "r"(sz) : "memory");
}

#define CP_COMMIT() asm volatile("cp.async.commit_group;" ::: "memory")
#define CP_WAIT1()  asm volatile("cp.async.wait_group 1;" ::: "memory")

#define LDSM_X4(r, addr) \
    asm volatile("ldmatrix.sync.aligned.m8n8.x4.shared.b16 {%0,%1,%2,%3}, [%4];" \
        : "=r"((r)[0]), "=r"((r)[1]), "=r"((r)[2]), "=r"((r)[3]) : "r"(addr))

__device__ __forceinline__ void mma_fp16(float* d, const uint32_t* a,
                                         uint32_t b0, uint32_t b1) {
    asm volatile(
        "mma.sync.aligned.m16n8k16.row.col.f32.f16.f16.f32 "
        "{%0,%1,%2,%3}, {%4,%5,%6,%7}, {%8,%9}, {%0,%1,%2,%3};"
        : "+f"(d[0]), "+f"(d[1]), "+f"(d[2]), "+f"(d[3])
        : "r"(a[0]), "r"(a[1]), "r"(a[2]), "r"(a[3]), "r"(b0), "r"(b1));
}

__device__ __forceinline__ float sigm_f(float v) { return 1.f / (1.f + __expf(-v)); }
__device__ __forceinline__ float tanh_f(float v) { return 2.f / (1.f + __expf(-2.f * v)) - 1.f; }

// ---------------------------------------------------------------------------
// Prep 1: transpose concat(x, prev_h) -> [b][y][x][ci] fp16 (float4 loads)
// ---------------------------------------------------------------------------
__global__ __launch_bounds__(256)
void prep_input_kernel(const float* __restrict__ x, const float* __restrict__ ph)
{
    __shared__ float s[64][129];
    const int bid = blockIdx.x;
    const int b = bid >> 7, y = bid & 127;
    const int tid = threadIdx.x;

    #pragma unroll
    for (int h2 = 0; h2 < 2; ++h2) {
        const int cbase = h2 * 64;
        for (int idx = tid; idx < 64 * 32; idx += 256) {
            int ci = idx >> 5, x4 = (idx & 31) * 4;
            int cs = cbase + ci;
            const float* src = (cs < CIN)
                ? (x  + ((size_t)b * CIN + cs) * HW)
                : (ph + ((size_t)b * CH + (cs - CIN)) * HW);
            float4 v = *reinterpret_cast<const float4*>(src + y * WW + x4);
            s[ci][x4]     = v.x;
            s[ci][x4 + 1] = v.y;
            s[ci][x4 + 2] = v.z;
            s[ci][x4 + 3] = v.w;
        }
        __syncthreads();
        for (int idx = tid; idx < 128 * 32; idx += 256) {
            int xx = idx >> 5, cp = (idx & 31) * 2;
            __half2 v = __floats2half2_rn(s[cp][xx], s[cp + 1][xx]);
            size_t o = ((size_t)(b * HH + y) * WW + xx) * CS + cbase + cp;
            *reinterpret_cast<__half2*>(g_inT + o) = v;
        }
        __syncthreads();
    }
}

// ---------------------------------------------------------------------------
// Prep 2: weights -> [n][k=tap*128+cs], fp16, gate-interleaved N order:
//   n = (c>>5)*128 + gate*32 + (c&31)   (oc = gate*64 + c)
// ---------------------------------------------------------------------------
__global__ __launch_bounds__(256)
void prep_w_kernel(const float* __restrict__ Wg)
{
    int idx = blockIdx.x * blockDim.x + threadIdx.x;
    if (idx >= COUT * KTOT) return;
    int n = idx / KTOT, k = idx - n * KTOT;
    int tap = k >> 7, cs = k & 127;
    int chblk = n >> 7, gate = (n >> 5) & 3, cl = n & 31;
    int oc = gate * 64 + chblk * 32 + cl;
    g_w[idx] = __float2half_rn(Wg[(size_t)oc * KTOT + cs * 9 + tap]);
}

// ---------------------------------------------------------------------------
// Main: implicit-GEMM conv (fp16) + fused LSTM gating.
// CTA tile M=128 x N=128, K=1152; 2 CTAs/SM (16 warps/SM).
// 256 threads = 8 warps in 2(M) x 4(N); warp tile 64x32.
// A: single buffer (one ci-half = rows y-1..y+1), reloaded at chunk 9.
// B: 3-stage cp.async ring, ONE __syncthreads per chunk.
// ---------------------------------------------------------------------------
__device__ __forceinline__ void issue_A_half(int half, uint32_t sb,
                                             int b, int y, int tid)
{
    const int ci0 = half * 64;
    // 3 rows x 130 px x 8 segs = 3120 cp.async
    #pragma unroll
    for (int q = 0; q < 13; ++q) {
        int idx = q * 256 + tid;
        if (idx < 3120) {
            int r = idx / 1040;                  // row 0..2
            int rem = idx - r * 1040;
            int pxi = rem >> 3, seg = rem & 7;   // pxi 0..129 -> px = pxi-1
            int yy = y + r - 1;
            int px = pxi - 1;
            bool valid = ((unsigned)yy < (unsigned)HH) &
                         ((unsigned)px < (unsigned)WW);
            int yc = ((unsigned)yy < (unsigned)HH) ? yy : 0;
            int xc = ((unsigned)px < (unsigned)WW) ? px : 0;
            const void* src = g_inT + (((size_t)(b * HH + yc) * WW + xc) * CS
                                       + ci0 + seg * 8);
            uint32_t dst = sb + r * AROW + pxi * PITCH + seg * 16;
            cp16(dst, src, valid);
        }
    }
}

__device__ __forceinline__ void issue_B(int chunk, uint32_t sb, int n0, int tid)
{
    const int half = chunk / 9, tap = chunk - half * 9;
    const uint32_t bbase = sb + OFF_B + (chunk % NBSTG) * B_TILE;
    // 128 rows x 8 segs = 1024 -> 4/thread
    #pragma unroll
    for (int q = 0; q < 4; ++q) {
        int idx = q * 256 + tid;
        int n = idx >> 3, seg = idx & 7;
        const void* src = g_w + ((size_t)(n0 + n) * KTOT + tap * 128 + half * 64
                                 + seg * 8);
        uint32_t dst = bbase + n * PITCH + seg * 16;
        cp16(dst, src, true);
    }
}

__global__ __launch_bounds__(256, 2)
void convlstm_mma_kernel(const float* __restrict__ prev_c,
                         const float* __restrict__ bg,
                         float* __restrict__ out)
{
    extern __shared__ char smem[];
    const uint32_t sb = smem_to_u32(smem);
    const int tid = threadIdx.x, wid = tid >> 5, lane = tid & 31;
    const int bid = blockIdx.x;
    const int nhalf = bid & 1;
    const int y = (bid >> 1) & 127, b = bid >> 8;
    const int nb0 = nhalf * NT;           // weight-row origin
    const int m0 = (wid & 1) * 64;        // warp m origin (2 m-warps, 64 px)
    const int n0w = (wid >> 1) * 32;      // warp n origin (4 n-warps, 32 n)

    float acc[4][4][4];
    #pragma unroll
    for (int i = 0; i < 4; ++i)
        #pragma unroll
        for (int j = 0; j < 4; ++j)
            #pragma unroll
            for (int t = 0; t < 4; ++t) acc[i][j][t] = 0.f;

    // Prologue: g1 = {A(half0), B0}, g2 = {B1}
    issue_A_half(0, sb, b, y, tid);
    issue_B(0, sb, nb0, tid);
    CP_COMMIT();
    issue_B(1, sb, nb0, tid);
    CP_COMMIT();

    for (int c = 0; c < NCHUNK; ++c) {
        CP_WAIT1();                // second-to-last group done -> B(c) ready
        __syncthreads();           // cross-thread visibility + stage reuse
        if (c == 9) {
            // A(half0) fully consumed (compute(8) done by all warps above).
            issue_A_half(1, sb, b, y, tid);
            CP_COMMIT();                       // own group
            if (c + 2 < NCHUNK) issue_B(c + 2, sb, nb0, tid);
            CP_COMMIT();
            CP_WAIT1();            // force A(half1) group complete
            __syncthreads();       // visibility of A(half1)
        } else {
            if (c + 2 < NCHUNK) issue_B(c + 2, sb, nb0, tid);
            CP_COMMIT();
        }

        const int half = c / 9, tap = c - half * 9;
        const int ky = tap / 3, kx = tap - ky * 3;
        const uint32_t Arow = sb + ky * AROW;
        const uint32_t Bt = sb + OFF_B + (c % NBSTG) * B_TILE;
        (void)half;

        #pragma unroll
        for (int s = 0; s < 4; ++s) {           // 4 x k16 steps per chunk
            uint32_t af[4][4];
            #pragma unroll
            for (int i = 0; i < 4; ++i) {
                // staged px index = px + 1; read px = m + kx - 1
                uint32_t r = m0 + i * 16 + (lane & 15) + kx;
                uint32_t off = r * PITCH + s * 32 + (lane >> 4) * 16;
                LDSM_X4(af[i], Arow + off);
            }
            uint32_t bf[2][4];
            #pragma unroll
            for (int j2 = 0; j2 < 2; ++j2) {    // 2 n16 blocks
                uint32_t n = n0w + j2 * 16 + ((lane >> 4) << 3) + (lane & 7);
                uint32_t off = n * PITCH + s * 32 + ((lane >> 3) & 1) * 16;
                LDSM_X4(bf[j2], Bt + off);
            }
            #pragma unroll
            for (int i = 0; i < 4; ++i)
                #pragma unroll
                for (int j = 0; j < 4; ++j) {   // 4 n8 tiles
                    uint32_t b0 = bf[j >> 1][(j & 1) * 2];
                    uint32_t b1 = bf[j >> 1][(j & 1) * 2 + 1];
                    mma_fp16(acc[i][j], af[i], b0, b1);
                }
        }
    }
    __syncthreads();               // all warps done reading A/B smem

    // ---- epilogue: acc -> smem gate staging [px][n] fp32, pitch 129 ----
    float* sg = (float*)smem;
    #pragma unroll
    for (int i = 0; i < 4; ++i)
        #pragma unroll
        for (int j = 0; j < 4; ++j) {
            int row = m0 + i * 16 + (lane >> 2);
            int col = n0w + j * 8 + (lane & 3) * 2;
            sg[row * GPITCH + col]           = acc[i][j][0];
            sg[row * GPITCH + col + 1]       = acc[i][j][1];
            sg[(row + 8) * GPITCH + col]     = acc[i][j][2];
            sg[(row + 8) * GPITCH + col + 1] = acc[i][j][3];
        }
    __syncthreads();

    // ---- fused LSTM gating: 128 px x 32 channels, all 4 gates local ----
    const int px = tid & 127;
    const int grp = tid >> 7;                 // 0..1
    #pragma unroll
    for (int t = 0; t < 16; ++t) {
        int cl = grp * 16 + t;                // 0..31
        float gi = sg[px * GPITCH + cl]       + __ldg(&bg[nhalf * 32 + cl]);
        float gf = sg[px * GPITCH + 32 + cl]  + __ldg(&bg[64 + nhalf * 32 + cl]);
        float go = sg[px * GPITCH + 64 + cl]  + __ldg(&bg[128 + nhalf * 32 + cl]);
        float gg = sg[px * GPITCH + 96 + cl]  + __ldg(&bg[192 + nhalf * 32 + cl]);
        float ig = sigm_f(gi), fg = sigm_f(gf), og = sigm_f(go), cg = tanh_f(gg);
        int cgl = nhalf * 32 + cl;
        size_t idx = ((size_t)(b * CH + cgl)) * HW + y * WW + px;
        float pc = prev_c[idx];
        float cell = ig * cg + fg * pc;
        float hid  = og * tanh_f(cell);
        out[idx] = hid;
        out[(size_t)NTOT + idx] = cell;
    }
}

// ---------------------------------------------------------------------------
extern "C" void kernel_launch(void* const* d_in, const int* in_sizes, int n_in,
                              void* d_out, int out_size)
{
    const float* x      = (const float*)d_in[0];
    const float* prev_h = (const float*)d_in[1];
    const float* prev_c = (const float*)d_in[2];
    const float* Wg     = (const float*)d_in[3];
    const float* bg     = (const float*)d_in[4];
    float* out = (float*)d_out;

    static bool attr_done = false;
    if (!attr_done) {
        cudaFuncSetAttribute(convlstm_mma_kernel,
                             cudaFuncAttributeMaxDynamicSharedMemorySize, SMEM_TOTAL);
        attr_done = true;
    }

    prep_input_kernel<<<B * HH, 256>>>(x, prev_h);
    prep_w_kernel<<<(COUT * KTOT + 255) / 256, 256>>>(Wg);
    convlstm_mma_kernel<<<B * HH * 2, 256, SMEM_TOTAL>>>(prev_c, bg, out);
}